// round 5
// baseline (speedup 1.0000x reference)
#include <cuda_runtime.h>

#define NV 50000
#define GD 10
#define GH 162
#define GW 162
#define NPART 240

// ---------------- device scratch (no allocations allowed) ----------------
__device__ int    g_grid[2 * GD * GH * GW];              // padded hash grid
__device__ int    g_nbr[27 * NV];                        // rulebook [k][n]
__device__ float4 g_phi[(NV + 1) * 64];                  // expanded features; pad row = phi(0)
__device__ __align__(16) float g_wc[27 * 256 * 128];     // combined weights [k][4Cin][Cout]
__device__ __align__(16) float g_raw[NV * 128];          // pre-BN conv output
__device__ float  g_part[NPART * 2 * 128];               // BN partial sums
__device__ float  g_mu[128];
__device__ float  g_istd[128];

// ---------------- small utility kernels ----------------
__global__ void k_zero4(float4* p, long n4) {
    long i = (long)blockIdx.x * blockDim.x + threadIdx.x;
    if (i < n4) p[i] = make_float4(0.f, 0.f, 0.f, 0.f);
}

__global__ void k_initgrid() {
    int i = blockIdx.x * blockDim.x + threadIdx.x;
    if (i < 2 * GD * GH * GW) g_grid[i] = NV;   // sentinel = NV (pad row)
}

__global__ void k_scatgrid(const int* __restrict__ coors) {
    int n = blockIdx.x * blockDim.x + threadIdx.x;
    if (n >= NV) return;
    int b = coors[4 * n], z = coors[4 * n + 1], y = coors[4 * n + 2], x = coors[4 * n + 3];
    g_grid[((b * GD + z + 1) * GH + y + 1) * GW + x + 1] = n;
}

__global__ void k_nbr(const int* __restrict__ coors) {
    int n = blockIdx.x * blockDim.x + threadIdx.x;
    if (n >= NV) return;
    int b = coors[4 * n], z = coors[4 * n + 1] + 1, y = coors[4 * n + 2] + 1, x = coors[4 * n + 3] + 1;
    int k = 0;
#pragma unroll
    for (int dz = -1; dz <= 1; dz++)
#pragma unroll
        for (int dy = -1; dy <= 1; dy++)
#pragma unroll
            for (int dx = -1; dx <= 1; dx++) {
                g_nbr[k * NV + n] = g_grid[((b * GD + z + dz) * GH + y + dy) * GW + x + dx];
                k++;
            }
}

// phi(x) = (silu(x), exp(-(x+1)^2), exp(-x^2), exp(-(x-1)^2))   [centers -1,0,1, inv_h=1]
__device__ __forceinline__ float4 phi_of(float x) {
    float s  = x / (1.f + expf(-x));
    float b0 = expf(-(x + 1.f) * (x + 1.f));
    float b1 = expf(-x * x);
    float b2 = expf(-(x - 1.f) * (x - 1.f));
    return make_float4(s, b0, b1, b2);
}

// layer-1 phi from external voxel features; pad row n==NV gets phi(0)
__global__ void k_phi_in(const float* __restrict__ ext) {
    int t = blockIdx.x * blockDim.x + threadIdx.x;
    if (t >= (NV + 1) * 16) return;
    float x = (t < NV * 16) ? ext[t] : 0.f;
    g_phi[t] = phi_of(x);
}

// fused BN(train stats) + ReLU + phi expansion for intermediate layers
template <int COUT>
__global__ void k_bnphi(const float* __restrict__ gm, const float* __restrict__ bt) {
    long t = (long)blockIdx.x * 256 + threadIdx.x;
    if (t >= (long)(NV + 1) * COUT) return;
    float x = 0.f;
    if (t < (long)NV * COUT) {
        int col = (int)(t % COUT);
        float v = (g_raw[t] - g_mu[col]) * g_istd[col] * gm[col] + bt[col];
        x = fmaxf(v, 0.f);
    }
    g_phi[t] = phi_of(x);
}

// fused BN + ReLU + dense scatter for the final layer: out[b, c*8+z, y, x]
__global__ void k_bnscat(const int* __restrict__ coors,
                         const float* __restrict__ gm, const float* __restrict__ bt,
                         float* __restrict__ out) {
    long t = (long)blockIdx.x * 256 + threadIdx.x;
    if (t >= (long)NV * 128) return;
    int n = (int)(t >> 7);
    int c = (int)(t & 127);
    float v = (g_raw[t] - g_mu[c]) * g_istd[c] * gm[c] + bt[c];
    v = fmaxf(v, 0.f);
    int b = coors[4 * n], z = coors[4 * n + 1], y = coors[4 * n + 2], x = coors[4 * n + 3];
    long oi = (((long)(b * 1024 + c * 8 + z)) * 160 + y) * 160 + x;
    out[oi] = v;
}

// Combined weight: Wc[k][c*4+0][o]=wb[k,c,o];  Wc[k][c*4+1+g][o]=ws[k,c,g,o]
template <int CIN, int COUT>
__global__ void k_wc(const float* __restrict__ wb, const float* __restrict__ ws) {
    int t = blockIdx.x * blockDim.x + threadIdx.x;
    if (t >= 27 * 4 * CIN * COUT) return;
    int o = t % COUT;
    int r = t / COUT;
    int j = r % (4 * CIN);
    int k = r / (4 * CIN);
    int c = j >> 2, jj = j & 3;
    g_wc[t] = (jj == 0) ? wb[(k * CIN + c) * COUT + o]
                        : ws[((k * CIN + c) * 3 + (jj - 1)) * COUT + o];
}

// ---------------- gather-GEMM: M-packed f32x2, weights pre-duplicated in SMEM ----------------
__device__ __forceinline__ unsigned long long ffma2(unsigned long long a,
                                                    unsigned long long b,
                                                    unsigned long long c) {
    unsigned long long d;
    asm("fma.rn.f32x2 %0, %1, %2, %3;" : "=l"(d) : "l"(a), "l"(b), "l"(c));
    return d;
}

__device__ __forceinline__ unsigned long long dup2(float x) {
    unsigned long long r;
    unsigned int u = __float_as_uint(x);
    asm("mov.b64 %0, {%1, %1};" : "=l"(r) : "r"(u));
    return r;
}

// out[m, o] = sum_k sum_j phi[nbr[k][m]][j] * Wc[k][j][o]
// CTA tile: TM voxels x COUT cols, 256 threads. Each thread: 8 voxels (4 f32x2
// M-pairs) x TN contiguous cols. Weights staged DUPLICATED ((w,w) 8B entries) so
// the inner loop is pure LDS.128 + FFMA2: per j, 2 broadcast A loads + TN/2
// B loads + 4*TN FFMA2.
template <int CIN, int COUT, int TM, int TN>
__global__ __launch_bounds__(256) void k_gemm() {
    constexpr int KD  = 4 * CIN;         // reduction length per tap
    constexpr int KC  = 32;              // k-chunk
    constexpr int CPT = KD / KC;         // chunks per tap
    constexpr int TNG = COUT / TN;       // thread groups along N
    constexpr int TPR = 256 / TM;        // threads cooperating per A row
    constexpr int JW  = KC / TPR;        // floats gathered per thread
    constexpr int WPT = KC * COUT / 256; // dup'd weights stored per thread
    static_assert((256 / TNG) * 8 == TM, "tiling");
    static_assert(JW % 4 == 0 && TN % 2 == 0, "vec");

    __shared__ __align__(16) float As[KC][TM];
    __shared__ __align__(16) unsigned long long Wd[KC][COUT];   // duplicated weights
    __shared__ int sIdx[TM];

    int tid  = threadIdx.x;
    int tx   = tid % TNG;
    int ty   = tid / TNG;
    int row0 = ty * 8;
    int m0   = blockIdx.x * TM;
    int arow = tid / TPR;
    int aj0  = (tid % TPR) * JW;

    unsigned long long acc[4][TN];
#pragma unroll
    for (int p = 0; p < 4; p++)
#pragma unroll
        for (int i = 0; i < TN; i++) acc[p][i] = 0ull;

    for (int k = 0; k < 27; k++) {
        __syncthreads();
        if (tid < TM) {
            int m = m0 + tid;
            sIdx[tid] = (m < NV) ? g_nbr[k * NV + m] : NV;   // NV -> phi(0) pad row
        }
        __syncthreads();
        const float*  wck  = g_wc + (size_t)k * KD * COUT;
        const float4* prow = g_phi + (size_t)sIdx[arow] * CIN;

        for (int jc = 0; jc < KD; jc += KC) {
            // gather A chunk [KC x TM] (j-major, voxels contiguous)
#pragma unroll
            for (int q = 0; q < JW / 4; q++) {
                float4 v = prow[((jc + aj0) >> 2) + q];
                As[aj0 + q * 4 + 0][arow] = v.x;
                As[aj0 + q * 4 + 1][arow] = v.y;
                As[aj0 + q * 4 + 2][arow] = v.z;
                As[aj0 + q * 4 + 3][arow] = v.w;
            }
            // stage W chunk duplicated: Wd[j][o] = (w, w)
            const float* wsrc = wck + (size_t)jc * COUT;
#pragma unroll
            for (int q = 0; q < WPT; q++)
                ((unsigned long long*)Wd)[tid + q * 256] = dup2(wsrc[tid + q * 256]);
            __syncthreads();

#pragma unroll
            for (int j = 0; j < KC; j++) {
                // 8 voxels as 4 f32x2 pairs (broadcast LDS.128)
                ulonglong2 pa = *(const ulonglong2*)&As[j][row0];
                ulonglong2 pb = *(const ulonglong2*)&As[j][row0 + 4];
                unsigned long long b[TN];
#pragma unroll
                for (int u = 0; u < TN / 2; u++) {
                    ulonglong2 t2 = ((const ulonglong2*)&Wd[j][tx * TN])[u];
                    b[2 * u]     = t2.x;
                    b[2 * u + 1] = t2.y;
                }
#pragma unroll
                for (int i = 0; i < TN; i++) {
                    acc[0][i] = ffma2(pa.x, b[i], acc[0][i]);
                    acc[1][i] = ffma2(pa.y, b[i], acc[1][i]);
                    acc[2][i] = ffma2(pb.x, b[i], acc[2][i]);
                    acc[3][i] = ffma2(pb.y, b[i], acc[3][i]);
                }
            }
            __syncthreads();
        }
    }

    // epilogue: cols tx*TN..+TN-1 contiguous -> vectorized stores per voxel row
#pragma unroll
    for (int p = 0; p < 4; p++) {
        int r = m0 + row0 + 2 * p;
        float lo[TN], hi[TN];
#pragma unroll
        for (int i = 0; i < TN; i++) {
            unsigned int l, h;
            asm("mov.b64 {%0, %1}, %2;" : "=r"(l), "=r"(h) : "l"(acc[p][i]));
            lo[i] = __uint_as_float(l);
            hi[i] = __uint_as_float(h);
        }
        float* o0 = g_raw + (size_t)r * COUT + tx * TN;
        float* o1 = o0 + COUT;
        if (TN == 4) {
            if (r < NV)     *(float4*)o0 = make_float4(lo[0], lo[1], lo[2], lo[3]);
            if (r + 1 < NV) *(float4*)o1 = make_float4(hi[0], hi[1], hi[2], hi[3]);
        } else {
            if (r < NV)     *(float2*)o0 = make_float2(lo[0], lo[1]);
            if (r + 1 < NV) *(float2*)o1 = make_float2(hi[0], hi[1]);
        }
    }
}

// ---------------- BatchNorm statistics (deterministic tree reduction) ----------------
template <int COUT>
__global__ void k_stats1() {
    constexpr int RP = 256 / COUT;
    int tid = threadIdx.x;
    int col = tid % COUT, rg = tid / COUT;
    float s = 0.f, q = 0.f;
    for (int r = blockIdx.x * RP + rg; r < NV; r += NPART * RP) {
        float v = g_raw[(size_t)r * COUT + col];
        s += v;
        q += v * v;
    }
    __shared__ float sh[256], sh2[256];
    sh[tid] = s; sh2[tid] = q;
    __syncthreads();
    if (rg == 0) {
#pragma unroll
        for (int g2 = 1; g2 < RP; g2++) { s += sh[g2 * COUT + col]; q += sh2[g2 * COUT + col]; }
        g_part[blockIdx.x * 2 * COUT + col]        = s;
        g_part[blockIdx.x * 2 * COUT + COUT + col] = q;
    }
}

template <int COUT>
__global__ void k_stats2() {
    int col = threadIdx.x;
    if (col >= COUT) return;
    double s = 0.0, q = 0.0;
    for (int b = 0; b < NPART; b++) {
        s += (double)g_part[b * 2 * COUT + col];
        q += (double)g_part[b * 2 * COUT + COUT + col];
    }
    double mu  = s / (double)NV;
    double var = q / (double)NV - mu * mu;
    g_mu[col]   = (float)mu;
    g_istd[col] = (float)(1.0 / sqrt(var + 1e-3));
}

// ---------------- host orchestration ----------------
template <int CIN, int COUT, int TM, int TN>
static void run_gemm_block(const float* wb, const float* ws) {
    k_wc<CIN, COUT><<<(27 * 4 * CIN * COUT + 255) / 256, 256>>>(wb, ws);
    k_gemm<CIN, COUT, TM, TN><<<(NV + TM - 1) / TM, 256>>>();
    k_stats1<COUT><<<NPART, 256>>>();
    k_stats2<COUT><<<1, 128>>>();
}

extern "C" void kernel_launch(void* const* d_in, const int* in_sizes, int n_in,
                              void* d_out, int out_size) {
    const float* vf    = (const float*)d_in[0];
    const int*   coors = (const int*)d_in[1];
    // d_in[2] = batch_size (compile-time B=2)
    const float *wb[5], *ws[5], *gm[5], *bt[5];
    for (int i = 0; i < 5; i++) {
        wb[i] = (const float*)d_in[3 + 4 * i];
        ws[i] = (const float*)d_in[4 + 4 * i];
        gm[i] = (const float*)d_in[5 + 4 * i];
        bt[i] = (const float*)d_in[6 + 4 * i];
    }

    // rulebook first (5 setup launches -> ncu -s 5 -c 1 captures the 6th = first GEMM)
    k_initgrid<<<(2 * GD * GH * GW + 255) / 256, 256>>>();
    k_scatgrid<<<(NV + 255) / 256, 256>>>(coors);
    k_nbr<<<(NV + 255) / 256, 256>>>(coors);
    k_phi_in<<<(((NV + 1) * 16) + 255) / 256, 256>>>(vf);

    k_wc<16, 16><<<(27 * 4 * 16 * 16 + 255) / 256, 256>>>(wb[0], ws[0]);
    k_gemm<16, 16, 256, 2><<<(NV + 255) / 256, 256>>>();
    k_stats1<16><<<NPART, 256>>>();
    k_stats2<16><<<1, 128>>>();
    k_bnphi<16><<<(int)((((long)(NV + 1) * 16) + 255) / 256), 256>>>(gm[0], bt[0]);

    run_gemm_block<16, 32, 128, 2>(wb[1], ws[1]);
    k_bnphi<32><<<(int)((((long)(NV + 1) * 32) + 255) / 256), 256>>>(gm[1], bt[1]);

    run_gemm_block<32, 64, 128, 4>(wb[2], ws[2]);
    k_bnphi<64><<<(int)((((long)(NV + 1) * 64) + 255) / 256), 256>>>(gm[2], bt[2]);

    run_gemm_block<64, 64, 128, 4>(wb[3], ws[3]);
    k_bnphi<64><<<(int)((((long)(NV + 1) * 64) + 255) / 256), 256>>>(gm[3], bt[3]);

    run_gemm_block<64, 128, 64, 4>(wb[4], ws[4]);

    // zero dense output (poisoned by harness), then fused BN+ReLU+scatter
    long n4 = (long)out_size / 4;
    k_zero4<<<(int)((n4 + 255) / 256), 256>>>((float4*)d_out, n4);
    k_bnscat<<<(int)((((long)NV * 128) + 255) / 256), 256>>>(coors, gm[4], bt[4], (float*)d_out);
}

// round 6
// speedup vs baseline: 1.6907x; 1.6907x over previous
#include <cuda_runtime.h>

#define NV 50000
#define GD 10
#define GH 162
#define GW 162
#define NPART 240

// ---------------- device scratch (no allocations allowed) ----------------
__device__ int    g_grid[2 * GD * GH * GW];              // padded hash grid
__device__ int    g_nbr[27 * NV];                        // rulebook [k][n]
__device__ float4 g_phi[(NV + 1) * 64];                  // expanded features; pad row = phi(0)
__device__ __align__(16) float g_wc[27 * 256 * 128];     // combined weights [k][4Cin][Cout]
__device__ __align__(16) float g_raw[NV * 128];          // pre-BN conv output
__device__ float  g_part[NPART * 2 * 128];               // BN partial sums
__device__ float  g_mu[128];
__device__ float  g_istd[128];

// ---------------- small utility kernels ----------------
__global__ void k_zero4(float4* p, long n4) {
    long i = (long)blockIdx.x * blockDim.x + threadIdx.x;
    if (i < n4) p[i] = make_float4(0.f, 0.f, 0.f, 0.f);
}

__global__ void k_initgrid() {
    int i = blockIdx.x * blockDim.x + threadIdx.x;
    if (i < 2 * GD * GH * GW) g_grid[i] = NV;   // sentinel = NV (pad row)
}

__global__ void k_scatgrid(const int* __restrict__ coors) {
    int n = blockIdx.x * blockDim.x + threadIdx.x;
    if (n >= NV) return;
    int b = coors[4 * n], z = coors[4 * n + 1], y = coors[4 * n + 2], x = coors[4 * n + 3];
    g_grid[((b * GD + z + 1) * GH + y + 1) * GW + x + 1] = n;
}

__global__ void k_nbr(const int* __restrict__ coors) {
    int n = blockIdx.x * blockDim.x + threadIdx.x;
    if (n >= NV) return;
    int b = coors[4 * n], z = coors[4 * n + 1] + 1, y = coors[4 * n + 2] + 1, x = coors[4 * n + 3] + 1;
    int k = 0;
#pragma unroll
    for (int dz = -1; dz <= 1; dz++)
#pragma unroll
        for (int dy = -1; dy <= 1; dy++)
#pragma unroll
            for (int dx = -1; dx <= 1; dx++) {
                g_nbr[k * NV + n] = g_grid[((b * GD + z + dz) * GH + y + dy) * GW + x + dx];
                k++;
            }
}

// phi(x) = (silu(x), exp(-(x+1)^2), exp(-x^2), exp(-(x-1)^2))   [centers -1,0,1, inv_h=1]
__device__ __forceinline__ float4 phi_of(float x) {
    float s  = x / (1.f + expf(-x));
    float b0 = expf(-(x + 1.f) * (x + 1.f));
    float b1 = expf(-x * x);
    float b2 = expf(-(x - 1.f) * (x - 1.f));
    return make_float4(s, b0, b1, b2);
}

// layer-1 phi from external voxel features; pad row n==NV gets phi(0)
__global__ void k_phi_in(const float* __restrict__ ext) {
    int t = blockIdx.x * blockDim.x + threadIdx.x;
    if (t >= (NV + 1) * 16) return;
    float x = (t < NV * 16) ? ext[t] : 0.f;
    g_phi[t] = phi_of(x);
}

// fused BN(train stats) + ReLU + phi expansion for intermediate layers
template <int COUT>
__global__ void k_bnphi(const float* __restrict__ gm, const float* __restrict__ bt) {
    long t = (long)blockIdx.x * 256 + threadIdx.x;
    if (t >= (long)(NV + 1) * COUT) return;
    float x = 0.f;
    if (t < (long)NV * COUT) {
        int col = (int)(t % COUT);
        float v = (g_raw[t] - g_mu[col]) * g_istd[col] * gm[col] + bt[col];
        x = fmaxf(v, 0.f);
    }
    g_phi[t] = phi_of(x);
}

// fused BN + ReLU + dense scatter for the final layer: out[b, c*8+z, y, x]
__global__ void k_bnscat(const int* __restrict__ coors,
                         const float* __restrict__ gm, const float* __restrict__ bt,
                         float* __restrict__ out) {
    long t = (long)blockIdx.x * 256 + threadIdx.x;
    if (t >= (long)NV * 128) return;
    int n = (int)(t >> 7);
    int c = (int)(t & 127);
    float v = (g_raw[t] - g_mu[c]) * g_istd[c] * gm[c] + bt[c];
    v = fmaxf(v, 0.f);
    int b = coors[4 * n], z = coors[4 * n + 1], y = coors[4 * n + 2], x = coors[4 * n + 3];
    long oi = (((long)(b * 1024 + c * 8 + z)) * 160 + y) * 160 + x;
    out[oi] = v;
}

// Combined weight: Wc[k][c*4+0][o]=wb[k,c,o];  Wc[k][c*4+1+g][o]=ws[k,c,g,o]
template <int CIN, int COUT>
__global__ void k_wc(const float* __restrict__ wb, const float* __restrict__ ws) {
    int t = blockIdx.x * blockDim.x + threadIdx.x;
    if (t >= 27 * 4 * CIN * COUT) return;
    int o = t % COUT;
    int r = t / COUT;
    int j = r % (4 * CIN);
    int k = r / (4 * CIN);
    int c = j >> 2, jj = j & 3;
    g_wc[t] = (jj == 0) ? wb[(k * CIN + c) * COUT + o]
                        : ws[((k * CIN + c) * 3 + (jj - 1)) * COUT + o];
}

// ---------------- gather-GEMM with packed f32x2 FMA (R2 structure, big tiles) ----------------
__device__ __forceinline__ unsigned long long ffma2(unsigned long long a,
                                                    unsigned long long b,
                                                    unsigned long long c) {
    unsigned long long d;
    asm("fma.rn.f32x2 %0, %1, %2, %3;" : "=l"(d) : "l"(a), "l"(b), "l"(c));
    return d;
}

// out[m, o] = sum_k sum_j phi[nbr[k][m]][j] * Wc[k][j][o]
// CTA tile: TM voxels x COUT cols, 256 threads; each thread 8 voxels (4 f32x2
// M-pairs) x TN cols. A reads: warp-broadcast LDS.128 (conflict-free). W reads:
// scalar LDS at 4B lane stride (conflict-free) + dup mov. Tiles sized so
// bytes/FMA = 4(1/TM + 1/COUT) stays under the ~6300 B/cyc LTS cap.
template <int CIN, int COUT, int TM, int TN>
__global__ __launch_bounds__(256) void k_gemm() {
    constexpr int KD  = 4 * CIN;      // reduction length per tap
    constexpr int KC  = 32;           // k-chunk
    constexpr int TNG = COUT / TN;    // thread groups along N
    constexpr int TPR = 256 / TM;     // threads cooperating per A row
    constexpr int JW  = KC / TPR;     // floats gathered per thread
    static_assert((256 / TNG) * 8 == TM, "tiling");
    static_assert(JW % 4 == 0, "vec");

    __shared__ __align__(16) float As[KC][TM];
    __shared__ __align__(16) float Ws[KC][COUT];
    __shared__ int sIdx[TM];

    int tid  = threadIdx.x;
    int tx   = tid % TNG;
    int ty   = tid / TNG;
    int row0 = ty * 8;
    int m0   = blockIdx.x * TM;
    int arow = tid / TPR;
    int aj0  = (tid % TPR) * JW;

    unsigned long long acc[4][TN];
#pragma unroll
    for (int p = 0; p < 4; p++)
#pragma unroll
        for (int i = 0; i < TN; i++) acc[p][i] = 0ull;

    for (int k = 0; k < 27; k++) {
        __syncthreads();
        if (TM == 256 || tid < TM) {
            int m = m0 + tid;
            sIdx[tid] = (m < NV) ? g_nbr[k * NV + m] : NV;   // NV -> phi(0) pad row
        }
        __syncthreads();
        const float*  wck  = g_wc + (size_t)k * KD * COUT;
        const float4* prow = g_phi + (size_t)sIdx[arow] * CIN;

        for (int jc = 0; jc < KD; jc += KC) {
            // gather A chunk [KC x TM] (store transposed: j-major, m contiguous)
#pragma unroll
            for (int q = 0; q < JW / 4; q++) {
                float4 v = prow[((jc + aj0) >> 2) + q];
                As[aj0 + q * 4 + 0][arow] = v.x;
                As[aj0 + q * 4 + 1][arow] = v.y;
                As[aj0 + q * 4 + 2][arow] = v.z;
                As[aj0 + q * 4 + 3][arow] = v.w;
            }
            // load W chunk [KC x COUT], fully coalesced
            const float4* w4 = (const float4*)(wck + jc * COUT);
#pragma unroll 4
            for (int q = tid; q < KC * COUT / 4; q += 256) ((float4*)Ws)[q] = w4[q];
            __syncthreads();

#pragma unroll
            for (int j = 0; j < KC; j++) {
                // 8 voxels of A as 4 f32x2 pairs (warp-broadcast LDS.128, conflict-free)
                ulonglong2 pa = *(const ulonglong2*)&As[j][row0];
                ulonglong2 pb = *(const ulonglong2*)&As[j][row0 + 4];
#pragma unroll
                for (int i = 0; i < TN; i++) {
                    unsigned int bi = __float_as_uint(Ws[j][tx + i * TNG]);
                    unsigned long long b2;
                    asm("mov.b64 %0, {%1, %1};" : "=l"(b2) : "r"(bi));
                    acc[0][i] = ffma2(pa.x, b2, acc[0][i]);
                    acc[1][i] = ffma2(pa.y, b2, acc[1][i]);
                    acc[2][i] = ffma2(pb.x, b2, acc[2][i]);
                    acc[3][i] = ffma2(pb.y, b2, acc[3][i]);
                }
            }
            __syncthreads();
        }
    }

    // epilogue: unpack f32x2 pairs, store pre-BN output
#pragma unroll
    for (int p = 0; p < 4; p++) {
        int r = m0 + row0 + 2 * p;
#pragma unroll
        for (int i = 0; i < TN; i++) {
            unsigned int lo, hi;
            asm("mov.b64 {%0, %1}, %2;" : "=r"(lo), "=r"(hi) : "l"(acc[p][i]));
            int col = tx + i * TNG;
            if (r < NV)     g_raw[(size_t)r * COUT + col]       = __uint_as_float(lo);
            if (r + 1 < NV) g_raw[(size_t)(r + 1) * COUT + col] = __uint_as_float(hi);
        }
    }
}

// ---------------- BatchNorm statistics (deterministic tree reduction) ----------------
template <int COUT>
__global__ void k_stats1() {
    constexpr int RP = 256 / COUT;
    int tid = threadIdx.x;
    int col = tid % COUT, rg = tid / COUT;
    float s = 0.f, q = 0.f;
    for (int r = blockIdx.x * RP + rg; r < NV; r += NPART * RP) {
        float v = g_raw[(size_t)r * COUT + col];
        s += v;
        q += v * v;
    }
    __shared__ float sh[256], sh2[256];
    sh[tid] = s; sh2[tid] = q;
    __syncthreads();
    if (rg == 0) {
#pragma unroll
        for (int g2 = 1; g2 < RP; g2++) { s += sh[g2 * COUT + col]; q += sh2[g2 * COUT + col]; }
        g_part[blockIdx.x * 2 * COUT + col]        = s;
        g_part[blockIdx.x * 2 * COUT + COUT + col] = q;
    }
}

template <int COUT>
__global__ void k_stats2() {
    int col = threadIdx.x;
    if (col >= COUT) return;
    double s = 0.0, q = 0.0;
    for (int b = 0; b < NPART; b++) {
        s += (double)g_part[b * 2 * COUT + col];
        q += (double)g_part[b * 2 * COUT + COUT + col];
    }
    double mu  = s / (double)NV;
    double var = q / (double)NV - mu * mu;
    g_mu[col]   = (float)mu;
    g_istd[col] = (float)(1.0 / sqrt(var + 1e-3));
}

// ---------------- host orchestration ----------------
template <int CIN, int COUT, int TM, int TN>
static void run_gemm_block(const float* wb, const float* ws) {
    k_wc<CIN, COUT><<<(27 * 4 * CIN * COUT + 255) / 256, 256>>>(wb, ws);
    k_gemm<CIN, COUT, TM, TN><<<(NV + TM - 1) / TM, 256>>>();
    k_stats1<COUT><<<NPART, 256>>>();
    k_stats2<COUT><<<1, 128>>>();
}

extern "C" void kernel_launch(void* const* d_in, const int* in_sizes, int n_in,
                              void* d_out, int out_size) {
    const float* vf    = (const float*)d_in[0];
    const int*   coors = (const int*)d_in[1];
    // d_in[2] = batch_size (compile-time B=2)
    const float *wb[5], *ws[5], *gm[5], *bt[5];
    for (int i = 0; i < 5; i++) {
        wb[i] = (const float*)d_in[3 + 4 * i];
        ws[i] = (const float*)d_in[4 + 4 * i];
        gm[i] = (const float*)d_in[5 + 4 * i];
        bt[i] = (const float*)d_in[6 + 4 * i];
    }

    // rulebook + layer-1 phi (5 setup launches before the first GEMM)
    k_initgrid<<<(2 * GD * GH * GW + 255) / 256, 256>>>();
    k_scatgrid<<<(NV + 255) / 256, 256>>>(coors);
    k_nbr<<<(NV + 255) / 256, 256>>>(coors);
    k_phi_in<<<(((NV + 1) * 16) + 255) / 256, 256>>>(vf);

    // L1: 16 -> 16
    run_gemm_block<16, 16, 256, 2>(wb[0], ws[0]);
    k_bnphi<16><<<(int)((((long)(NV + 1) * 16) + 255) / 256), 256>>>(gm[0], bt[0]);

    // L2: 16 -> 32
    run_gemm_block<16, 32, 256, 4>(wb[1], ws[1]);
    k_bnphi<32><<<(int)((((long)(NV + 1) * 32) + 255) / 256), 256>>>(gm[1], bt[1]);

    // L3: 32 -> 64
    run_gemm_block<32, 64, 128, 4>(wb[2], ws[2]);
    k_bnphi<64><<<(int)((((long)(NV + 1) * 64) + 255) / 256), 256>>>(gm[2], bt[2]);

    // L4: 64 -> 64
    run_gemm_block<64, 64, 128, 4>(wb[3], ws[3]);
    k_bnphi<64><<<(int)((((long)(NV + 1) * 64) + 255) / 256), 256>>>(gm[3], bt[3]);

    // L5: 64 -> 128
    run_gemm_block<64, 128, 128, 8>(wb[4], ws[4]);

    // zero dense output (poisoned by harness), then fused BN+ReLU+scatter
    long n4 = (long)out_size / 4;
    k_zero4<<<(int)((n4 + 255) / 256), 256>>>((float4*)d_out, n4);
    k_bnscat<<<(int)((((long)NV * 128) + 255) / 256), 256>>>(coors, gm[4], bt[4], (float*)d_out);
}